// round 15
// baseline (speedup 1.0000x reference)
#include <cuda_runtime.h>
#include <cuda_fp16.h>
#include <cstdint>

#define SEQ    2048
#define BATCH  2
#define DIMC   1024
#define NHEAD  16
#define HDIM   64
#define MROWS  (BATCH * SEQ)   // 4096
#define QKW    (DIMC / 2)      // 512 u32 (half2) pair-words per row

// Scratch (device globals: no allocation allowed)
__device__ uint32_t g_qh[MROWS * QKW];    // half2(0.125*q), packed along d
__device__ uint32_t g_kh[MROWS * QKW];    // half2(k), packed along d
__device__ __half   g_vt[DIMC * MROWS];   // V transposed: VT[c][r]
__device__ float    g_o [MROWS * DIMC];   // attn output fp32
__device__ uint32_t g_xh[MROWS * QKW];    // x split hi (packed fp16x2)
__device__ uint32_t g_xl[MROWS * QKW];    // x split lo
__device__ uint32_t g_wh[4 * DIMC * QKW]; // Wq,Wk,Wv,Wp rounded fp16 (packed)
__device__ uint32_t g_oh[MROWS * QKW];    // attn out split hi
__device__ uint32_t g_ol[MROWS * QKW];    // attn out split lo

__device__ __forceinline__ uint32_t packh(float lo, float hi) {
    uint32_t d;
    asm("cvt.rn.f16x2.f32 %0, %1, %2;" : "=r"(d) : "f"(hi), "f"(lo));
    return d;
}

// fp16 m16n8k16
__device__ __forceinline__ void mma16f(float c[4], const uint32_t a[4],
                                       uint32_t b0, uint32_t b1) {
    asm volatile(
        "mma.sync.aligned.m16n8k16.row.col.f32.f16.f16.f32 "
        "{%0,%1,%2,%3}, {%4,%5,%6,%7}, {%8,%9}, {%0,%1,%2,%3};"
        : "+f"(c[0]), "+f"(c[1]), "+f"(c[2]), "+f"(c[3])
        : "r"(a[0]), "r"(a[1]), "r"(a[2]), "r"(a[3]), "r"(b0), "r"(b1));
}

// Split float2 (adjacent k values) into packed fp16x2 hi + lo parts.
__device__ __forceinline__ void hsplit(float2 v, uint32_t& h, uint32_t& l) {
    h = packh(v.x, v.y);
    __half2 hh = *reinterpret_cast<__half2*>(&h);
    float f0 = __low2float(hh), f1 = __high2float(hh);
    l = packh(v.x - f0, v.y - f1);
}

__device__ __forceinline__ void cp_async16(uint32_t saddr, const void* gaddr) {
    asm volatile("cp.async.ca.shared.global [%0], [%1], 16;" :: "r"(saddr), "l"(gaddr));
}

// ============================================================================
// Elementwise prep kernels (bandwidth-bound, ~2-5 us each)
// ============================================================================
__global__ void splitpair_kernel(const float* __restrict__ src,
                                 uint32_t* __restrict__ h, uint32_t* __restrict__ l,
                                 int npairs) {
    int i = blockIdx.x * blockDim.x + threadIdx.x;
    if (i < npairs) {
        float2 v = ((const float2*)src)[i];
        uint32_t hh, ll;
        hsplit(v, hh, ll);
        h[i] = hh; l[i] = ll;
    }
}

__global__ void roundpair_kernel(const float* __restrict__ src,
                                 uint32_t* __restrict__ h, int npairs) {
    int i = blockIdx.x * blockDim.x + threadIdx.x;
    if (i < npairs) {
        float2 v = ((const float2*)src)[i];
        h[i] = packh(v.x, v.y);
    }
}

// ============================================================================
// 2xFP16 GEMM, pre-split operands, pure LDS+MMA inner loop.
// C = A @ W^T; A = half2 hi/lo packed along k; W = half2 rounded.
// Block 256x128, BK=32 (16 pair-words), 512 threads (16 warps, 4x4),
// warp tile 64x32. 3-stage cp.async ring, prefetch distance 2.
// smem stage (u32 words): Ah 256x20 | Al 256x20 | Bh 128x20 = 12800 words.
// mode: 0 = fp32 + bias, 1 = half2(v) to Ch, 2 = half2(0.125 v) to Ch,
//       3 = transposed half to VT[c][r]
// ============================================================================
#define GS_AH 0
#define GS_AL (256 * 20)
#define GS_BH (512 * 20)
#define GSTAGE_W (512 * 20 + 128 * 20)     // 12800 words per stage
#define GEMM_SMEM (3 * GSTAGE_W * 4)        // 153600 B

__global__ __launch_bounds__(512, 1)
void gemm_ps(const uint32_t* __restrict__ Ahp, const uint32_t* __restrict__ Alp,
             const uint32_t* __restrict__ Whp,
             float* __restrict__ Cf, uint32_t* __restrict__ Ch,
             __half* __restrict__ Cv,
             const float* __restrict__ bias, int mode) {
    extern __shared__ uint32_t gsm[];

    const int tid  = threadIdx.x;
    const int lane = tid & 31;
    const int warp = tid >> 5;
    const int wm   = warp >> 2;      // 0..3 (64-row strip)
    const int wn   = warp & 3;       // 0..3 (32-col strip)
    const int m0   = blockIdx.y * 256;
    const int n0   = blockIdx.x * 128;

    float acc[4][4][4];
#pragma unroll
    for (int i = 0; i < 4; i++)
#pragma unroll
        for (int j = 0; j < 4; j++)
#pragma unroll
            for (int k = 0; k < 4; k++) acc[i][j][k] = 0.f;

    const uint32_t smBase = (uint32_t)__cvta_generic_to_shared(gsm);

    // staging roles
    const int aArr = tid & 1;          // 0 = hi, 1 = lo
    const int aRow = tid >> 1;         // 0..255
    const int bRow = tid >> 2;         // 0..127
    const int bCh  = tid & 3;          // 0..3

    auto prefetch = [&](int tile, int stage) {
        const uint32_t so = (uint32_t)stage * (GSTAGE_W * 4u);
        const int gp = tile * 16;      // pair-word offset of this BK=32 slab
        const uint32_t* aSrc = (aArr ? Alp : Ahp) + (size_t)(m0 + aRow) * QKW + gp;
        const uint32_t aDst = smBase + so + (uint32_t)((aArr ? GS_AL : GS_AH) + aRow * 20) * 4u;
#pragma unroll
        for (int c = 0; c < 4; c++)
            cp_async16(aDst + c * 16u, aSrc + c * 4);
        const uint32_t* bSrc = Whp + (size_t)(n0 + bRow) * QKW + gp + bCh * 4;
        cp_async16(smBase + so + (uint32_t)(GS_BH + bRow * 20 + bCh * 4) * 4u, bSrc);
        asm volatile("cp.async.commit_group;");
    };

    const int NT = DIMC / 32;   // 32
    prefetch(0, 0);
    prefetch(1, 1);

    int stage = 0;
    for (int kt = 0; kt < NT; kt++) {
        if (kt + 1 < NT) asm volatile("cp.async.wait_group 1;");
        else             asm volatile("cp.async.wait_group 0;");
        __syncthreads();

        const uint32_t* st = gsm + stage * GSTAGE_W;
        const uint32_t (*AhS)[20] = (const uint32_t(*)[20])(st + GS_AH);
        const uint32_t (*AlS)[20] = (const uint32_t(*)[20])(st + GS_AL);
        const uint32_t (*BhS)[20] = (const uint32_t(*)[20])(st + GS_BH);

#pragma unroll
        for (int ks = 0; ks < 2; ks++) {
            const int pp = ks * 8 + (lane & 3);
            uint32_t ah[4][4], al[4][4];
#pragma unroll
            for (int mt = 0; mt < 4; mt++) {
                int r = wm * 64 + mt * 16 + (lane >> 2);
                ah[mt][0] = AhS[r][pp];     ah[mt][1] = AhS[r + 8][pp];
                ah[mt][2] = AhS[r][pp + 4]; ah[mt][3] = AhS[r + 8][pp + 4];
                al[mt][0] = AlS[r][pp];     al[mt][1] = AlS[r + 8][pp];
                al[mt][2] = AlS[r][pp + 4]; al[mt][3] = AlS[r + 8][pp + 4];
            }
#pragma unroll
            for (int nt = 0; nt < 4; nt++) {
                int nn = wn * 32 + nt * 8 + (lane >> 2);
                uint32_t bh0 = BhS[nn][pp], bh1 = BhS[nn][pp + 4];
#pragma unroll
                for (int mt = 0; mt < 4; mt++) {
                    mma16f(acc[mt][nt], ah[mt], bh0, bh1);
                    mma16f(acc[mt][nt], al[mt], bh0, bh1);
                }
            }
        }

        if (kt + 2 < NT) {
            int ns = stage + 2; if (ns >= 3) ns -= 3;
            prefetch(kt + 2, ns);
        }
        stage++; if (stage == 3) stage = 0;
    }

#pragma unroll
    for (int mt = 0; mt < 4; mt++) {
#pragma unroll
        for (int nt = 0; nt < 4; nt++) {
            int r = m0 + wm * 64 + mt * 16 + (lane >> 2);
            int c = n0 + wn * 32 + nt * 8 + (lane & 3) * 2;
            float v0 = acc[mt][nt][0], v1 = acc[mt][nt][1];
            float v2 = acc[mt][nt][2], v3 = acc[mt][nt][3];
            if (mode == 0) {
                float bb0 = bias[c], bb1 = bias[c + 1];
                *(float2*)&Cf[(size_t)r       * DIMC + c] = make_float2(v0 + bb0, v1 + bb1);
                *(float2*)&Cf[(size_t)(r + 8) * DIMC + c] = make_float2(v2 + bb0, v3 + bb1);
            } else if (mode == 1) {
                Ch[(size_t)r       * QKW + (c >> 1)] = packh(v0, v1);
                Ch[(size_t)(r + 8) * QKW + (c >> 1)] = packh(v2, v3);
            } else if (mode == 2) {
                Ch[(size_t)r       * QKW + (c >> 1)] = packh(0.125f * v0, 0.125f * v1);
                Ch[(size_t)(r + 8) * QKW + (c >> 1)] = packh(0.125f * v2, 0.125f * v3);
            } else {
                Cv[(size_t)c       * MROWS + r]     = __float2half(v0);
                Cv[(size_t)(c + 1) * MROWS + r]     = __float2half(v1);
                Cv[(size_t)c       * MROWS + r + 8] = __float2half(v2);
                Cv[(size_t)(c + 1) * MROWS + r + 8] = __float2half(v3);
            }
        }
    }
}

// ============================================================================
// Flash attention, fp16 m16n8k16, P in registers (unchanged from R12).
// ============================================================================
__global__ __launch_bounds__(128)
void attn_kernel(const uint32_t* __restrict__ Qh, const uint32_t* __restrict__ Kh,
                 const uint32_t* __restrict__ VT, float* __restrict__ O) {
    __shared__ uint32_t sm[2][2][64][36];   // [stage][K=0/V=1][row][word]

    const int tid  = threadIdx.x;
    const int lane = tid & 31;
    const int warp = tid >> 5;
    const int bh   = blockIdx.y;
    const int b    = bh >> 4;
    const int h    = bh & 15;
    const int q0   = blockIdx.x * 128;

    const uint32_t smBase = (uint32_t)__cvta_generic_to_shared(sm);

    auto prefetchKV = [&](int t, int s) {
        const int k0 = t * 64;
#pragma unroll
        for (int i = 0; i < 4; i++) {
            int idx = tid + i * 128;
            int row = idx >> 3, ch = idx & 7;
            const uint32_t* gk = Kh + (size_t)(b * SEQ + k0 + row) * QKW + h * 32 + ch * 4;
            cp_async16(smBase + (uint32_t)(((s * 2 + 0) * 64 + row) * 36 + ch * 4) * 4u, gk);
            const uint32_t* gv = VT + (size_t)(h * HDIM + row) * (MROWS / 2)
                                    + ((b * SEQ + k0) >> 1) + ch * 4;
            cp_async16(smBase + (uint32_t)(((s * 2 + 1) * 64 + row) * 36 + ch * 4) * 4u, gv);
        }
        asm volatile("cp.async.commit_group;");
    };

    prefetchKV(0, 0);

    uint32_t qf[2][4][4];
#pragma unroll
    for (int s = 0; s < 2; s++) {
        int qr = b * SEQ + q0 + warp * 32 + s * 16 + (lane >> 2);
        const uint32_t* qp0 = Qh + (size_t)qr * QKW + h * 32;
        const uint32_t* qp1 = qp0 + (size_t)8 * QKW;
#pragma unroll
        for (int j = 0; j < 4; j++) {
            int w = j * 8 + (lane & 3);
            qf[s][j][0] = qp0[w];
            qf[s][j][1] = qp1[w];
            qf[s][j][2] = qp0[w + 4];
            qf[s][j][3] = qp1[w + 4];
        }
    }

    float o0[8][4], o1[8][4];
#pragma unroll
    for (int i = 0; i < 8; i++)
#pragma unroll
        for (int j = 0; j < 4; j++) { o0[i][j] = 0.f; o1[i][j] = 0.f; }
    float l0l = 0.f, l0h = 0.f, l1l = 0.f, l1h = 0.f;

    for (int t = 0; t < SEQ / 64; t++) {
        const int buf = t & 1;
        __syncthreads();
        if (t + 1 < SEQ / 64) {
            prefetchKV(t + 1, buf ^ 1);
            asm volatile("cp.async.wait_group 1;");
        } else {
            asm volatile("cp.async.wait_group 0;");
        }
        __syncthreads();

        const uint32_t (*Ks)[36] = sm[buf][0];
        const uint32_t (*Vs)[36] = sm[buf][1];

        float s0[8][4], s1[8][4];
#pragma unroll
        for (int i = 0; i < 8; i++)
#pragma unroll
            for (int j = 0; j < 4; j++) { s0[i][j] = 0.f; s1[i][j] = 0.f; }
#pragma unroll
        for (int j = 0; j < 4; j++) {
            const int w = j * 8 + (lane & 3);
#pragma unroll
            for (int nt = 0; nt < 8; nt++) {
                int key = nt * 8 + (lane >> 2);
                uint32_t b0 = Ks[key][w];
                uint32_t b1 = Ks[key][w + 4];
                mma16f(s0[nt], qf[0][j], b0, b1);
                mma16f(s1[nt], qf[1][j], b0, b1);
            }
        }

        uint32_t pa0[4][4], pa1[4][4];
#pragma unroll
        for (int nt = 0; nt < 8; nt++) {
            float e0 = __expf(s0[nt][0]), e1 = __expf(s0[nt][1]);
            float e2 = __expf(s0[nt][2]), e3 = __expf(s0[nt][3]);
            l0l += e0 + e1; l0h += e2 + e3;
            pa0[nt >> 1][(nt & 1) * 2 + 0] = packh(e0, e1);
            pa0[nt >> 1][(nt & 1) * 2 + 1] = packh(e2, e3);
            float f0 = __expf(s1[nt][0]), f1 = __expf(s1[nt][1]);
            float f2 = __expf(s1[nt][2]), f3 = __expf(s1[nt][3]);
            l1l += f0 + f1; l1h += f2 + f3;
            pa1[nt >> 1][(nt & 1) * 2 + 0] = packh(f0, f1);
            pa1[nt >> 1][(nt & 1) * 2 + 1] = packh(f2, f3);
        }

#pragma unroll
        for (int j = 0; j < 4; j++) {
            const int w = j * 8 + (lane & 3);
#pragma unroll
            for (int nt = 0; nt < 8; nt++) {
                int d = nt * 8 + (lane >> 2);
                uint32_t b0 = Vs[d][w];
                uint32_t b1 = Vs[d][w + 4];
                mma16f(o0[nt], pa0[j], b0, b1);
                mma16f(o1[nt], pa1[j], b0, b1);
            }
        }
    }

    l0l += __shfl_xor_sync(0xffffffffu, l0l, 1);
    l0l += __shfl_xor_sync(0xffffffffu, l0l, 2);
    l0h += __shfl_xor_sync(0xffffffffu, l0h, 1);
    l0h += __shfl_xor_sync(0xffffffffu, l0h, 2);
    l1l += __shfl_xor_sync(0xffffffffu, l1l, 1);
    l1l += __shfl_xor_sync(0xffffffffu, l1l, 2);
    l1h += __shfl_xor_sync(0xffffffffu, l1h, 1);
    l1h += __shfl_xor_sync(0xffffffffu, l1h, 2);
    float il0l = 1.f / l0l, il0h = 1.f / l0h;
    float il1l = 1.f / l1l, il1h = 1.f / l1h;

    const size_t base = ((size_t)b * SEQ) * DIMC + (size_t)h * HDIM;
    const int or0 = q0 + warp * 32 + (lane >> 2);
#pragma unroll
    for (int nt = 0; nt < 8; nt++) {
        int d = nt * 8 + (lane & 3) * 2;
        *(float2*)&O[base + (size_t)or0        * DIMC + d] =
            make_float2(o0[nt][0] * il0l, o0[nt][1] * il0l);
        *(float2*)&O[base + (size_t)(or0 + 8)  * DIMC + d] =
            make_float2(o0[nt][2] * il0h, o0[nt][3] * il0h);
        *(float2*)&O[base + (size_t)(or0 + 16) * DIMC + d] =
            make_float2(o1[nt][0] * il1l, o1[nt][1] * il1l);
        *(float2*)&O[base + (size_t)(or0 + 24) * DIMC + d] =
            make_float2(o1[nt][2] * il1h, o1[nt][3] * il1h);
    }
}

extern "C" void kernel_launch(void* const* d_in, const int* in_sizes, int n_in,
                              void* d_out, int out_size) {
    (void)in_sizes; (void)n_in; (void)out_size;
    const float* x  = (const float*)d_in[0];
    const float* Wq = (const float*)d_in[1];
    const float* Wk = (const float*)d_in[2];
    const float* Wv = (const float*)d_in[3];
    const float* Wp = (const float*)d_in[4];
    const float* bp = (const float*)d_in[5];
    float* out = (float*)d_out;

    uint32_t *qh, *kh, *xh, *xl, *wh, *oh, *ol;
    __half* vt;
    float* op;
    cudaGetSymbolAddress((void**)&qh, g_qh);
    cudaGetSymbolAddress((void**)&kh, g_kh);
    cudaGetSymbolAddress((void**)&vt, g_vt);
    cudaGetSymbolAddress((void**)&op, g_o);
    cudaGetSymbolAddress((void**)&xh, g_xh);
    cudaGetSymbolAddress((void**)&xl, g_xl);
    cudaGetSymbolAddress((void**)&wh, g_wh);
    cudaGetSymbolAddress((void**)&oh, g_oh);
    cudaGetSymbolAddress((void**)&ol, g_ol);

    cudaFuncSetAttribute(gemm_ps, cudaFuncAttributeMaxDynamicSharedMemorySize,
                         GEMM_SMEM);

    const int WPAIRS = DIMC * QKW;     // 524288 per weight matrix
    const int XPAIRS = MROWS * QKW;    // 2097152

    splitpair_kernel<<<(XPAIRS + 255) / 256, 256>>>(x, xh, xl, XPAIRS);
    roundpair_kernel<<<(WPAIRS + 255) / 256, 256>>>(Wq, wh + 0 * WPAIRS, WPAIRS);
    roundpair_kernel<<<(WPAIRS + 255) / 256, 256>>>(Wk, wh + 1 * WPAIRS, WPAIRS);
    roundpair_kernel<<<(WPAIRS + 255) / 256, 256>>>(Wv, wh + 2 * WPAIRS, WPAIRS);
    roundpair_kernel<<<(WPAIRS + 255) / 256, 256>>>(Wp, wh + 3 * WPAIRS, WPAIRS);

    dim3 ggrid(DIMC / 128, MROWS / 256);   // (8, 16) = 128 CTAs
    gemm_ps<<<ggrid, 512, GEMM_SMEM>>>(xh, xl, wh + 0 * WPAIRS,
                                       nullptr, qh, nullptr, nullptr, 2);
    gemm_ps<<<ggrid, 512, GEMM_SMEM>>>(xh, xl, wh + 1 * WPAIRS,
                                       nullptr, kh, nullptr, nullptr, 1);
    gemm_ps<<<ggrid, 512, GEMM_SMEM>>>(xh, xl, wh + 2 * WPAIRS,
                                       nullptr, nullptr, vt, nullptr, 3);
    attn_kernel<<<dim3(SEQ / 128, BATCH * NHEAD), 128>>>(qh, kh, (const uint32_t*)vt, op);
    splitpair_kernel<<<(XPAIRS + 255) / 256, 256>>>(op, oh, ol, XPAIRS);
    gemm_ps<<<ggrid, 512, GEMM_SMEM>>>(oh, ol, wh + 3 * WPAIRS,
                                       out, nullptr, nullptr, bp, 0);
}

// round 17
// speedup vs baseline: 1.3557x; 1.3557x over previous
#include <cuda_runtime.h>
#include <cuda_fp16.h>
#include <cstdint>

#define SEQ    2048
#define BATCH  2
#define DIMC   1024
#define NHEAD  16
#define HDIM   64
#define MROWS  (BATCH * SEQ)   // 4096
#define QKW    (DIMC / 2)      // 512 u32 (half2) pair-words per row

// Scratch (device globals: no allocation allowed)
__device__ uint32_t g_qh[MROWS * QKW];   // half2(0.125*q), packed along d
__device__ uint32_t g_kh[MROWS * QKW];   // half2(k), packed along d
__device__ __half   g_vt[DIMC * MROWS];  // V transposed: VT[c][r]
__device__ float    g_o [MROWS * DIMC];  // attn output fp32

__device__ __forceinline__ uint32_t packh(float lo, float hi) {
    uint32_t d;
    asm("cvt.rn.f16x2.f32 %0, %1, %2;" : "=r"(d) : "f"(hi), "f"(lo));
    return d;
}

// fp16 m16n8k16
__device__ __forceinline__ void mma16f(float c[4], const uint32_t a[4],
                                       uint32_t b0, uint32_t b1) {
    asm volatile(
        "mma.sync.aligned.m16n8k16.row.col.f32.f16.f16.f32 "
        "{%0,%1,%2,%3}, {%4,%5,%6,%7}, {%8,%9}, {%0,%1,%2,%3};"
        : "+f"(c[0]), "+f"(c[1]), "+f"(c[2]), "+f"(c[3])
        : "r"(a[0]), "r"(a[1]), "r"(a[2]), "r"(a[3]), "r"(b0), "r"(b1));
}

// Split float2 (adjacent k values) into packed fp16x2 hi + lo parts.
__device__ __forceinline__ void hsplit(float2 v, uint32_t& h, uint32_t& l) {
    h = packh(v.x, v.y);
    __half2 hh = *reinterpret_cast<__half2*>(&h);
    float f0 = __low2float(hh), f1 = __high2float(hh);
    l = packh(v.x - f0, v.y - f1);
}

__device__ __forceinline__ void cp_async16(uint32_t saddr, const void* gaddr) {
    asm volatile("cp.async.ca.shared.global [%0], [%1], 16;" :: "r"(saddr), "l"(gaddr));
}

// ============================================================================
// R12-proven GEMM core as an inline device function.
// TWO_PASS: 1 = A split fp16 hi+lo (2 MMA passes), 0 = A rounded (1 pass).
// W always rounded to fp16 at consume. fp32 staging, 3-stage cp.async ring.
// Block 256x128, BK=32, 8 warps (4x2), warp tile 64x64, 256 threads.
// Epilogue via functor-style mode switch at the call site.
// ============================================================================
#define GSTAGE_F (256 * 36 + 128 * 36)      // 13824 floats per stage
#define GEMM_SMEM (3 * GSTAGE_F * 4)

template <int TWO_PASS>
__device__ __forceinline__ void gemm_core(const float* __restrict__ A,
                                          const float* __restrict__ W,
                                          float* __restrict__ gsm,
                                          int m0, int n0,
                                          float acc[4][8][4]) {
    const int tid  = threadIdx.x;
    const int lane = tid & 31;
    const int warp = tid >> 5;
    const int wm   = warp >> 1;      // 0..3
    const int wn   = warp & 1;       // 0..1

    const int sr = tid >> 3;         // 0..31
    const int sc = (tid & 7) * 4;    // 0..28

    const float* gaA = A + (size_t)(m0 + sr) * DIMC + sc;
    const float* gaB = W + (size_t)(n0 + sr) * DIMC + sc;

    const uint32_t smBase = (uint32_t)__cvta_generic_to_shared(gsm);
    const uint32_t sA = smBase + (uint32_t)(sr * 36 + sc) * 4u;
    const uint32_t sB = smBase + (uint32_t)(256 * 36 + sr * 36 + sc) * 4u;
    const uint32_t rowChunkS = 32 * 36 * 4;
    const size_t   rowChunkG = (size_t)32 * DIMC;
    const uint32_t stageB = GSTAGE_F * 4;

    auto prefetch = [&](int tile, int stage) {
        const uint32_t so = (uint32_t)stage * stageB;
        const int go = tile * 32;
#pragma unroll
        for (int i = 0; i < 8; i++)
            cp_async16(sA + so + i * rowChunkS, gaA + go + i * rowChunkG);
#pragma unroll
        for (int i = 0; i < 4; i++)
            cp_async16(sB + so + i * rowChunkS, gaB + go + i * rowChunkG);
        asm volatile("cp.async.commit_group;");
    };

    const int NT = DIMC / 32;   // 32
    prefetch(0, 0);
    prefetch(1, 1);

    int stage = 0;
    for (int kt = 0; kt < NT; kt++) {
        if (kt + 1 < NT) asm volatile("cp.async.wait_group 1;");
        else             asm volatile("cp.async.wait_group 0;");
        __syncthreads();

        const float (*Ab)[36] = (const float(*)[36])(gsm + stage * GSTAGE_F);
        const float (*Bb)[36] = (const float(*)[36])(gsm + stage * GSTAGE_F + 256 * 36);

#pragma unroll
        for (int ks = 0; ks < 2; ks++) {
            const int kk2 = ks * 16 + (lane & 3) * 2;
            uint32_t ah[4][4], al[4][4];
#pragma unroll
            for (int mt = 0; mt < 4; mt++) {
                int r = wm * 64 + mt * 16 + (lane >> 2);
                if (TWO_PASS) {
                    hsplit(*(const float2*)&Ab[r][kk2],         ah[mt][0], al[mt][0]);
                    hsplit(*(const float2*)&Ab[r + 8][kk2],     ah[mt][1], al[mt][1]);
                    hsplit(*(const float2*)&Ab[r][kk2 + 8],     ah[mt][2], al[mt][2]);
                    hsplit(*(const float2*)&Ab[r + 8][kk2 + 8], ah[mt][3], al[mt][3]);
                } else {
                    float2 a0 = *(const float2*)&Ab[r][kk2];
                    float2 a1 = *(const float2*)&Ab[r + 8][kk2];
                    float2 a2 = *(const float2*)&Ab[r][kk2 + 8];
                    float2 a3 = *(const float2*)&Ab[r + 8][kk2 + 8];
                    ah[mt][0] = packh(a0.x, a0.y);
                    ah[mt][1] = packh(a1.x, a1.y);
                    ah[mt][2] = packh(a2.x, a2.y);
                    ah[mt][3] = packh(a3.x, a3.y);
                }
            }
#pragma unroll
            for (int nt = 0; nt < 8; nt++) {
                int nn = wn * 64 + nt * 8 + (lane >> 2);
                float2 w0 = *(const float2*)&Bb[nn][kk2];
                float2 w1 = *(const float2*)&Bb[nn][kk2 + 8];
                uint32_t bh0 = packh(w0.x, w0.y);
                uint32_t bh1 = packh(w1.x, w1.y);
#pragma unroll
                for (int mt = 0; mt < 4; mt++) {
                    mma16f(acc[mt][nt], ah[mt], bh0, bh1);
                    if (TWO_PASS) mma16f(acc[mt][nt], al[mt], bh0, bh1);
                }
            }
        }

        if (kt + 2 < NT) {
            int ns = stage + 2; if (ns >= 3) ns -= 3;
            prefetch(kt + 2, ns);
        }
        stage++; if (stage == 3) stage = 0;
    }
}

// ============================================================================
// Fused QKV projection: blockIdx.z selects weight/epilogue.
// z=0: Q (2-pass, half2(0.125 v) -> qh), z=1: K (2-pass, half2 -> kh),
// z=2: V (1-pass, transposed half -> vt).
// ============================================================================
__global__ __launch_bounds__(256, 1)
void gemm_qkv(const float* __restrict__ x,
              const float* __restrict__ Wq, const float* __restrict__ Wk,
              const float* __restrict__ Wv,
              uint32_t* __restrict__ qh, uint32_t* __restrict__ kh,
              __half* __restrict__ vt) {
    extern __shared__ float gsm[];
    const int z  = blockIdx.z;
    const int m0 = blockIdx.y * 256;
    const int n0 = blockIdx.x * 128;

    float acc[4][8][4];
#pragma unroll
    for (int i = 0; i < 4; i++)
#pragma unroll
        for (int j = 0; j < 8; j++)
#pragma unroll
            for (int k = 0; k < 4; k++) acc[i][j][k] = 0.f;

    const float* W = (z == 0) ? Wq : (z == 1) ? Wk : Wv;
    if (z == 2) gemm_core<0>(x, W, gsm, m0, n0, acc);
    else        gemm_core<1>(x, W, gsm, m0, n0, acc);

    const int lane = threadIdx.x & 31;
    const int warp = threadIdx.x >> 5;
    const int wm   = warp >> 1;
    const int wn   = warp & 1;

#pragma unroll
    for (int mt = 0; mt < 4; mt++) {
#pragma unroll
        for (int nt = 0; nt < 8; nt++) {
            int r = m0 + wm * 64 + mt * 16 + (lane >> 2);
            int c = n0 + wn * 64 + nt * 8 + (lane & 3) * 2;
            float v0 = acc[mt][nt][0], v1 = acc[mt][nt][1];
            float v2 = acc[mt][nt][2], v3 = acc[mt][nt][3];
            if (z == 0) {
                qh[(size_t)r       * QKW + (c >> 1)] = packh(0.125f * v0, 0.125f * v1);
                qh[(size_t)(r + 8) * QKW + (c >> 1)] = packh(0.125f * v2, 0.125f * v3);
            } else if (z == 1) {
                kh[(size_t)r       * QKW + (c >> 1)] = packh(v0, v1);
                kh[(size_t)(r + 8) * QKW + (c >> 1)] = packh(v2, v3);
            } else {
                vt[(size_t)c       * MROWS + r]     = __float2half(v0);
                vt[(size_t)(c + 1) * MROWS + r]     = __float2half(v1);
                vt[(size_t)c       * MROWS + r + 8] = __float2half(v2);
                vt[(size_t)(c + 1) * MROWS + r + 8] = __float2half(v3);
            }
        }
    }
}

// ============================================================================
// Final projection: out = o @ Wp^T + bias, single-pass fp16.
// ============================================================================
__global__ __launch_bounds__(256, 1)
void gemm_fin(const float* __restrict__ o, const float* __restrict__ Wp,
              float* __restrict__ out, const float* __restrict__ bias) {
    extern __shared__ float gsm[];
    const int m0 = blockIdx.y * 256;
    const int n0 = blockIdx.x * 128;

    float acc[4][8][4];
#pragma unroll
    for (int i = 0; i < 4; i++)
#pragma unroll
        for (int j = 0; j < 8; j++)
#pragma unroll
            for (int k = 0; k < 4; k++) acc[i][j][k] = 0.f;

    gemm_core<0>(o, Wp, gsm, m0, n0, acc);

    const int lane = threadIdx.x & 31;
    const int warp = threadIdx.x >> 5;
    const int wm   = warp >> 1;
    const int wn   = warp & 1;

#pragma unroll
    for (int mt = 0; mt < 4; mt++) {
#pragma unroll
        for (int nt = 0; nt < 8; nt++) {
            int r = m0 + wm * 64 + mt * 16 + (lane >> 2);
            int c = n0 + wn * 64 + nt * 8 + (lane & 3) * 2;
            float bb0 = bias[c], bb1 = bias[c + 1];
            *(float2*)&out[(size_t)r       * DIMC + c] =
                make_float2(acc[mt][nt][0] + bb0, acc[mt][nt][1] + bb1);
            *(float2*)&out[(size_t)(r + 8) * DIMC + c] =
                make_float2(acc[mt][nt][2] + bb0, acc[mt][nt][3] + bb1);
        }
    }
}

// ============================================================================
// Flash attention, fp16 m16n8k16, P in registers (unchanged from R12).
// ============================================================================
__global__ __launch_bounds__(128)
void attn_kernel(const uint32_t* __restrict__ Qh, const uint32_t* __restrict__ Kh,
                 const uint32_t* __restrict__ VT, float* __restrict__ O) {
    __shared__ uint32_t sm[2][2][64][36];   // [stage][K=0/V=1][row][word]

    const int tid  = threadIdx.x;
    const int lane = tid & 31;
    const int warp = tid >> 5;
    const int bh   = blockIdx.y;
    const int b    = bh >> 4;
    const int h    = bh & 15;
    const int q0   = blockIdx.x * 128;

    const uint32_t smBase = (uint32_t)__cvta_generic_to_shared(sm);

    auto prefetchKV = [&](int t, int s) {
        const int k0 = t * 64;
#pragma unroll
        for (int i = 0; i < 4; i++) {
            int idx = tid + i * 128;
            int row = idx >> 3, ch = idx & 7;
            const uint32_t* gk = Kh + (size_t)(b * SEQ + k0 + row) * QKW + h * 32 + ch * 4;
            cp_async16(smBase + (uint32_t)(((s * 2 + 0) * 64 + row) * 36 + ch * 4) * 4u, gk);
            const uint32_t* gv = VT + (size_t)(h * HDIM + row) * (MROWS / 2)
                                    + ((b * SEQ + k0) >> 1) + ch * 4;
            cp_async16(smBase + (uint32_t)(((s * 2 + 1) * 64 + row) * 36 + ch * 4) * 4u, gv);
        }
        asm volatile("cp.async.commit_group;");
    };

    prefetchKV(0, 0);

    uint32_t qf[2][4][4];
#pragma unroll
    for (int s = 0; s < 2; s++) {
        int qr = b * SEQ + q0 + warp * 32 + s * 16 + (lane >> 2);
        const uint32_t* qp0 = Qh + (size_t)qr * QKW + h * 32;
        const uint32_t* qp1 = qp0 + (size_t)8 * QKW;
#pragma unroll
        for (int j = 0; j < 4; j++) {
            int w = j * 8 + (lane & 3);
            qf[s][j][0] = qp0[w];
            qf[s][j][1] = qp1[w];
            qf[s][j][2] = qp0[w + 4];
            qf[s][j][3] = qp1[w + 4];
        }
    }

    float o0[8][4], o1[8][4];
#pragma unroll
    for (int i = 0; i < 8; i++)
#pragma unroll
        for (int j = 0; j < 4; j++) { o0[i][j] = 0.f; o1[i][j] = 0.f; }
    float l0l = 0.f, l0h = 0.f, l1l = 0.f, l1h = 0.f;

    for (int t = 0; t < SEQ / 64; t++) {
        const int buf = t & 1;
        __syncthreads();
        if (t + 1 < SEQ / 64) {
            prefetchKV(t + 1, buf ^ 1);
            asm volatile("cp.async.wait_group 1;");
        } else {
            asm volatile("cp.async.wait_group 0;");
        }
        __syncthreads();

        const uint32_t (*Ks)[36] = sm[buf][0];
        const uint32_t (*Vs)[36] = sm[buf][1];

        float s0[8][4], s1[8][4];
#pragma unroll
        for (int i = 0; i < 8; i++)
#pragma unroll
            for (int j = 0; j < 4; j++) { s0[i][j] = 0.f; s1[i][j] = 0.f; }
#pragma unroll
        for (int j = 0; j < 4; j++) {
            const int w = j * 8 + (lane & 3);
#pragma unroll
            for (int nt = 0; nt < 8; nt++) {
                int key = nt * 8 + (lane >> 2);
                uint32_t b0 = Ks[key][w];
                uint32_t b1 = Ks[key][w + 4];
                mma16f(s0[nt], qf[0][j], b0, b1);
                mma16f(s1[nt], qf[1][j], b0, b1);
            }
        }

        uint32_t pa0[4][4], pa1[4][4];
#pragma unroll
        for (int nt = 0; nt < 8; nt++) {
            float e0 = __expf(s0[nt][0]), e1 = __expf(s0[nt][1]);
            float e2 = __expf(s0[nt][2]), e3 = __expf(s0[nt][3]);
            l0l += e0 + e1; l0h += e2 + e3;
            pa0[nt >> 1][(nt & 1) * 2 + 0] = packh(e0, e1);
            pa0[nt >> 1][(nt & 1) * 2 + 1] = packh(e2, e3);
            float f0 = __expf(s1[nt][0]), f1 = __expf(s1[nt][1]);
            float f2 = __expf(s1[nt][2]), f3 = __expf(s1[nt][3]);
            l1l += f0 + f1; l1h += f2 + f3;
            pa1[nt >> 1][(nt & 1) * 2 + 0] = packh(f0, f1);
            pa1[nt >> 1][(nt & 1) * 2 + 1] = packh(f2, f3);
        }

#pragma unroll
        for (int j = 0; j < 4; j++) {
            const int w = j * 8 + (lane & 3);
#pragma unroll
            for (int nt = 0; nt < 8; nt++) {
                int d = nt * 8 + (lane >> 2);
                uint32_t b0 = Vs[d][w];
                uint32_t b1 = Vs[d][w + 4];
                mma16f(o0[nt], pa0[j], b0, b1);
                mma16f(o1[nt], pa1[j], b0, b1);
            }
        }
    }

    l0l += __shfl_xor_sync(0xffffffffu, l0l, 1);
    l0l += __shfl_xor_sync(0xffffffffu, l0l, 2);
    l0h += __shfl_xor_sync(0xffffffffu, l0h, 1);
    l0h += __shfl_xor_sync(0xffffffffu, l0h, 2);
    l1l += __shfl_xor_sync(0xffffffffu, l1l, 1);
    l1l += __shfl_xor_sync(0xffffffffu, l1l, 2);
    l1h += __shfl_xor_sync(0xffffffffu, l1h, 1);
    l1h += __shfl_xor_sync(0xffffffffu, l1h, 2);
    float il0l = 1.f / l0l, il0h = 1.f / l0h;
    float il1l = 1.f / l1l, il1h = 1.f / l1h;

    const size_t base = ((size_t)b * SEQ) * DIMC + (size_t)h * HDIM;
    const int or0 = q0 + warp * 32 + (lane >> 2);
#pragma unroll
    for (int nt = 0; nt < 8; nt++) {
        int d = nt * 8 + (lane & 3) * 2;
        *(float2*)&O[base + (size_t)or0        * DIMC + d] =
            make_float2(o0[nt][0] * il0l, o0[nt][1] * il0l);
        *(float2*)&O[base + (size_t)(or0 + 8)  * DIMC + d] =
            make_float2(o0[nt][2] * il0h, o0[nt][3] * il0h);
        *(float2*)&O[base + (size_t)(or0 + 16) * DIMC + d] =
            make_float2(o1[nt][0] * il1l, o1[nt][1] * il1l);
        *(float2*)&O[base + (size_t)(or0 + 24) * DIMC + d] =
            make_float2(o1[nt][2] * il1h, o1[nt][3] * il1h);
    }
}

extern "C" void kernel_launch(void* const* d_in, const int* in_sizes, int n_in,
                              void* d_out, int out_size) {
    (void)in_sizes; (void)n_in; (void)out_size;
    const float* x  = (const float*)d_in[0];
    const float* Wq = (const float*)d_in[1];
    const float* Wk = (const float*)d_in[2];
    const float* Wv = (const float*)d_in[3];
    const float* Wp = (const float*)d_in[4];
    const float* bp = (const float*)d_in[5];
    float* out = (float*)d_out;

    uint32_t *qh, *kh;
    __half* vt;
    float* op;
    cudaGetSymbolAddress((void**)&qh, g_qh);
    cudaGetSymbolAddress((void**)&kh, g_kh);
    cudaGetSymbolAddress((void**)&vt, g_vt);
    cudaGetSymbolAddress((void**)&op, g_o);

    cudaFuncSetAttribute(gemm_qkv, cudaFuncAttributeMaxDynamicSharedMemorySize,
                         GEMM_SMEM);
    cudaFuncSetAttribute(gemm_fin, cudaFuncAttributeMaxDynamicSharedMemorySize,
                         GEMM_SMEM);

    dim3 qkvgrid(DIMC / 128, MROWS / 256, 3);   // (8, 16, 3) = 384 CTAs
    gemm_qkv<<<qkvgrid, 256, GEMM_SMEM>>>(x, Wq, Wk, Wv, qh, kh, vt);
    attn_kernel<<<dim3(SEQ / 128, BATCH * NHEAD), 128>>>(qh, kh, (const uint32_t*)vt, op);
    dim3 fgrid(DIMC / 128, MROWS / 256);        // (8, 16) = 128 CTAs
    gemm_fin<<<fgrid, 256, GEMM_SMEM>>>(op, Wp, out, bp);
}